// round 1
// baseline (speedup 1.0000x reference)
#include <cuda_runtime.h>
#include <math.h>

#define B_CHAIN 16384
#define S_SIDE  15
#define NATM    (1 + B_CHAIN + B_CHAIN * S_SIDE)

// 3x4 affine transform: rotation r[9] row-major, translation t[3]
struct M34 { float r[9]; float t[3]; };

__device__ __forceinline__ M34 m_identity() {
    M34 m;
    m.r[0]=1.f; m.r[1]=0.f; m.r[2]=0.f;
    m.r[3]=0.f; m.r[4]=1.f; m.r[5]=0.f;
    m.r[6]=0.f; m.r[7]=0.f; m.r[8]=1.f;
    m.t[0]=0.f; m.t[1]=0.f; m.t[2]=0.f;
    return m;
}

// C = A * B (A applied after... A is the EARLIER transform: C = A @ B)
__device__ __forceinline__ M34 compose(const M34& A, const M34& B) {
    M34 C;
#pragma unroll
    for (int i = 0; i < 3; i++) {
#pragma unroll
        for (int j = 0; j < 3; j++) {
            C.r[i*3+j] = fmaf(A.r[i*3+0], B.r[0*3+j],
                          fmaf(A.r[i*3+1], B.r[1*3+j],
                               A.r[i*3+2] * B.r[2*3+j]));
        }
        C.t[i] = fmaf(A.r[i*3+0], B.t[0],
                  fmaf(A.r[i*3+1], B.t[1],
                   fmaf(A.r[i*3+2], B.t[2], A.t[i])));
    }
    return C;
}

__device__ __forceinline__ M34 shflup(const M34& v, int d) {
    M34 o;
#pragma unroll
    for (int k = 0; k < 9; k++) o.r[k] = __shfl_up_sync(0xffffffffu, v.r[k], d);
#pragma unroll
    for (int k = 0; k < 3; k++) o.t[k] = __shfl_up_sync(0xffffffffu, v.t[k], d);
    return o;
}

// Build per-node transform.
// bond (dt==2): Rx(a)*Rz(b)*T(c,0,0)*Rx(d), dofs = (a,b,c,d)
// jump (dt==1): T(x,y,z)*Rz(e)*Ry(f)*Rx(d), dofs=(x,y,z,d), f=full[n][4], e=full[n][5]
__device__ __forceinline__ M34 build_ht(int n,
                                        const float* __restrict__ dofs,
                                        const float* __restrict__ full_dofs,
                                        int dt) {
    if (dt == 2) {
        float4 dv = *(const float4*)(dofs + 4 * (n - 1));
        float sa, ca, sb, cb, sd, cd;
        sincosf(dv.x, &sa, &ca);
        sincosf(dv.y, &sb, &cb);
        sincosf(dv.w, &sd, &cd);
        float c = dv.z;
        M34 m;
        m.r[0] = cb;      m.r[1] = -cd * sb;                 m.r[2] = sd * sb;
        m.r[3] = ca * sb; m.r[4] = fmaf(cd*ca, cb, -sd*sa);  m.r[5] = fmaf(-sd*ca, cb, -cd*sa);
        m.r[6] = sa * sb; m.r[7] = fmaf(cd*sa, cb,  sd*ca);  m.r[8] = fmaf(-sd*sa, cb,  cd*ca);
        m.t[0] = c * cb;
        m.t[1] = c * ca * sb;
        m.t[2] = c * sa * sb;
        return m;
    } else if (dt == 1) {
        float4 dv = *(const float4*)(dofs + 4 * (n - 1));
        float f = full_dofs[9 * n + 4];
        float e = full_dofs[9 * n + 5];
        float sd, cd, sf, cf, se, ce;
        sincosf(dv.w, &sd, &cd);
        sincosf(f, &sf, &cf);
        sincosf(e, &se, &ce);
        M34 m;
        m.r[0] = ce * cf;  m.r[1] = fmaf(sd*ce, sf, -cd*se);  m.r[2] = fmaf(cd*ce, sf,  sd*se);
        m.r[3] = se * cf;  m.r[4] = fmaf(sd*se, sf,  cd*ce);  m.r[5] = fmaf(cd*se, sf, -sd*ce);
        m.r[6] = -sf;      m.r[7] = sd * cf;                  m.r[8] = cd * cf;
        m.t[0] = dv.x; m.t[1] = dv.y; m.t[2] = dv.z;
        return m;
    }
    return m_identity();
}

// Scratch (allocation-free: __device__ globals)
__device__ float g_L[12][B_CHAIN];        // backbone block-local inclusive products (SoA)
__device__ float g_Agg[128][12];          // per-block aggregates
__device__ float g_P[128][12];            // exclusive block prefixes
__device__ float g_St[S_SIDE][3][B_CHAIN];// side-chain local inclusive translations (SoA)

// Inclusive Kogge-Stone scan across 128 threads (4 warps)
__device__ __forceinline__ void block_scan_128(M34& v, int tid, M34* sAgg) {
    int lane = tid & 31, w = tid >> 5;
#pragma unroll
    for (int d = 1; d < 32; d <<= 1) {
        M34 o = shflup(v, d);
        if (lane >= d) v = compose(o, v);
    }
    if (lane == 31) sAgg[w] = v;
    __syncthreads();
    if (w > 0) {
        M34 p = sAgg[0];
        for (int k = 1; k < w; k++) p = compose(p, sAgg[k]);
        v = compose(p, v);
    }
}

// Phase 1: backbone block-local scans (blocks 0..127) + side-chain local scans (blocks 128..255)
__global__ void __launch_bounds__(128)
k_phase1(const float* __restrict__ dofs,
         const float* __restrict__ full_dofs,
         const int* __restrict__ doftype) {
    __shared__ M34 sAgg[4];
    int blk = blockIdx.x;
    int tid = threadIdx.x;

    if (blk < 128) {
        int t = blk * 128 + tid;       // 0..16383
        int n = t + 1;                 // backbone node 1..16384
        int dt = doftype[n];
        M34 v = build_ht(n, dofs, full_dofs, dt);
        block_scan_128(v, tid, sAgg);
#pragma unroll
        for (int c = 0; c < 9; c++) g_L[c][t] = v.r[c];
#pragma unroll
        for (int c = 0; c < 3; c++) g_L[9 + c][t] = v.t[c];
        if (tid == 127) {
#pragma unroll
            for (int c = 0; c < 9; c++) g_Agg[blk][c] = v.r[c];
#pragma unroll
            for (int c = 0; c < 3; c++) g_Agg[blk][9 + c] = v.t[c];
        }
    } else {
        int b = (blk - 128) * 128 + tid;  // chain id 0..16383
        M34 run;
#pragma unroll
        for (int s = 0; s < S_SIDE; s++) {
            int ns = 1 + B_CHAIN + b * S_SIDE + s;
            int dt = doftype[ns];
            M34 h = build_ht(ns, dofs, full_dofs, dt);
            run = (s == 0) ? h : compose(run, h);
            g_St[s][0][b] = run.t[0];
            g_St[s][1][b] = run.t[1];
            g_St[s][2][b] = run.t[2];
        }
    }
}

// Phase 2: exclusive scan of the 128 block aggregates (single block)
__global__ void __launch_bounds__(128)
k_phase2() {
    __shared__ M34 sAgg[4];
    int tid = threadIdx.x;
    M34 v;
#pragma unroll
    for (int c = 0; c < 9; c++) v.r[c] = g_Agg[tid][c];
#pragma unroll
    for (int c = 0; c < 3; c++) v.t[c] = g_Agg[tid][9 + c];
    block_scan_128(v, tid, sAgg);
    if (tid == 0) {
        M34 I = m_identity();
#pragma unroll
        for (int c = 0; c < 9; c++) g_P[0][c] = I.r[c];
#pragma unroll
        for (int c = 0; c < 3; c++) g_P[0][9 + c] = I.t[c];
    }
    if (tid < 127) {
#pragma unroll
        for (int c = 0; c < 9; c++) g_P[tid + 1][c] = v.r[c];
#pragma unroll
        for (int c = 0; c < 3; c++) g_P[tid + 1][9 + c] = v.t[c];
    }
}

// Phase 3: apply block prefixes; write backbone coords; fix up side-chain
// translations with a matvec (chain b's parent is backbone node b+1 == this thread's node)
__global__ void __launch_bounds__(128)
k_phase3(const int* __restrict__ kin_id, float* __restrict__ out) {
    int blk = blockIdx.x, tid = threadIdx.x;
    int t = blk * 128 + tid;   // 0..16383
    int n = t + 1;             // backbone node

    M34 P;
#pragma unroll
    for (int c = 0; c < 9; c++) P.r[c] = g_P[blk][c];
#pragma unroll
    for (int c = 0; c < 3; c++) P.t[c] = g_P[blk][9 + c];

    M34 L;
#pragma unroll
    for (int c = 0; c < 9; c++) L.r[c] = g_L[c][t];
#pragma unroll
    for (int c = 0; c < 3; c++) L.t[c] = g_L[9 + c][t];

    M34 G = compose(P, L);

    int kid = kin_id[n];
    out[3 * kid + 0] = G.t[0];
    out[3 * kid + 1] = G.t[1];
    out[3 * kid + 2] = G.t[2];

#pragma unroll
    for (int s = 0; s < S_SIDE; s++) {
        float x = g_St[s][0][t];
        float y = g_St[s][1][t];
        float z = g_St[s][2][t];
        float vx = fmaf(G.r[0], x, fmaf(G.r[1], y, fmaf(G.r[2], z, G.t[0])));
        float vy = fmaf(G.r[3], x, fmaf(G.r[4], y, fmaf(G.r[5], z, G.t[1])));
        float vz = fmaf(G.r[6], x, fmaf(G.r[7], y, fmaf(G.r[8], z, G.t[2])));
        int ns = 1 + B_CHAIN + t * S_SIDE + s;
        int k2 = kin_id[ns];
        out[3 * k2 + 0] = vx;
        out[3 * k2 + 1] = vy;
        out[3 * k2 + 2] = vz;
    }
}

extern "C" void kernel_launch(void* const* d_in, const int* in_sizes, int n_in,
                              void* d_out, int out_size) {
    const float* dofs      = (const float*)d_in[0];
    const float* full_dofs = (const float*)d_in[1];
    const int*   doftype   = (const int*)d_in[4];
    const int*   kin_id    = (const int*)d_in[8];
    float* out = (float*)d_out;

    k_phase1<<<256, 128>>>(dofs, full_dofs, doftype);
    k_phase2<<<1, 128>>>();
    k_phase3<<<128, 128>>>(kin_id, out);
}

// round 2
// speedup vs baseline: 1.6036x; 1.6036x over previous
#include <cuda_runtime.h>
#include <math.h>

#define B_CHAIN 16384
#define S_SIDE  15
#define NATM    (1 + B_CHAIN + B_CHAIN * S_SIDE)

// 3x4 affine transform: rotation r[9] row-major, translation t[3]
struct M34 { float r[9]; float t[3]; };

__device__ __forceinline__ M34 m_identity() {
    M34 m;
    m.r[0]=1.f; m.r[1]=0.f; m.r[2]=0.f;
    m.r[3]=0.f; m.r[4]=1.f; m.r[5]=0.f;
    m.r[6]=0.f; m.r[7]=0.f; m.r[8]=1.f;
    m.t[0]=0.f; m.t[1]=0.f; m.t[2]=0.f;
    return m;
}

// C = A @ B  (A is the earlier transform)
__device__ __forceinline__ M34 compose(const M34& A, const M34& B) {
    M34 C;
#pragma unroll
    for (int i = 0; i < 3; i++) {
#pragma unroll
        for (int j = 0; j < 3; j++) {
            C.r[i*3+j] = fmaf(A.r[i*3+0], B.r[0*3+j],
                          fmaf(A.r[i*3+1], B.r[1*3+j],
                               A.r[i*3+2] * B.r[2*3+j]));
        }
        C.t[i] = fmaf(A.r[i*3+0], B.t[0],
                  fmaf(A.r[i*3+1], B.t[1],
                   fmaf(A.r[i*3+2], B.t[2], A.t[i])));
    }
    return C;
}

__device__ __forceinline__ M34 shflup(const M34& v, int d, int width) {
    M34 o;
#pragma unroll
    for (int k = 0; k < 9; k++) o.r[k] = __shfl_up_sync(0xffffffffu, v.r[k], d, width);
#pragma unroll
    for (int k = 0; k < 3; k++) o.t[k] = __shfl_up_sync(0xffffffffu, v.t[k], d, width);
    return o;
}

// Build per-node transform (fast MUFU sincos).
// bond (dt==2): Rx(a)*Rz(b)*T(c,0,0)*Rx(d)  dofs=(a,b,c,d)
// jump (dt==1): T(x,y,z)*Rz(e)*Ry(f)*Rx(d)  dofs=(x,y,z,d), f=full[n][4], e=full[n][5]
__device__ __forceinline__ M34 build_ht(int n,
                                        const float* __restrict__ dofs,
                                        const float* __restrict__ full_dofs,
                                        int dt) {
    if (dt == 2) {
        float4 dv = *(const float4*)(dofs + 4 * (n - 1));
        float sa, ca, sb, cb, sd, cd;
        __sincosf(dv.x, &sa, &ca);
        __sincosf(dv.y, &sb, &cb);
        __sincosf(dv.w, &sd, &cd);
        float c = dv.z;
        M34 m;
        m.r[0] = cb;      m.r[1] = -cd * sb;                 m.r[2] = sd * sb;
        m.r[3] = ca * sb; m.r[4] = fmaf(cd*ca, cb, -sd*sa);  m.r[5] = fmaf(-sd*ca, cb, -cd*sa);
        m.r[6] = sa * sb; m.r[7] = fmaf(cd*sa, cb,  sd*ca);  m.r[8] = fmaf(-sd*sa, cb,  cd*ca);
        m.t[0] = c * cb;
        m.t[1] = c * ca * sb;
        m.t[2] = c * sa * sb;
        return m;
    } else if (dt == 1) {
        float4 dv = *(const float4*)(dofs + 4 * (n - 1));
        float f = full_dofs[9 * n + 4];
        float e = full_dofs[9 * n + 5];
        float sd, cd, sf, cf, se, ce;
        __sincosf(dv.w, &sd, &cd);
        __sincosf(f, &sf, &cf);
        __sincosf(e, &se, &ce);
        M34 m;
        m.r[0] = ce * cf;  m.r[1] = fmaf(sd*ce, sf, -cd*se);  m.r[2] = fmaf(cd*ce, sf,  sd*se);
        m.r[3] = se * cf;  m.r[4] = fmaf(sd*se, sf,  cd*ce);  m.r[5] = fmaf(cd*se, sf, -sd*ce);
        m.r[6] = -sf;      m.r[7] = sd * cf;                  m.r[8] = cd * cf;
        m.t[0] = dv.x; m.t[1] = dv.y; m.t[2] = dv.z;
        return m;
    }
    return m_identity();
}

// Scratch (allocation-free: __device__ globals)
__device__ float g_L[12][B_CHAIN];          // backbone block-local inclusive products (SoA)
__device__ float g_Agg[128][12];            // per-block aggregates
__device__ float g_P[128][12];              // exclusive block prefixes
__device__ float g_St[B_CHAIN][S_SIDE*3+1]; // side-chain inclusive translations (AoS, padded)

// Inclusive Kogge-Stone scan across 128 threads (4 warps)
__device__ __forceinline__ void block_scan_128(M34& v, int tid, M34* sAgg) {
    int lane = tid & 31, w = tid >> 5;
#pragma unroll
    for (int d = 1; d < 32; d <<= 1) {
        M34 o = shflup(v, d, 32);
        if (lane >= d) v = compose(o, v);
    }
    if (lane == 31) sAgg[w] = v;
    __syncthreads();
    if (w > 0) {
        M34 p = sAgg[0];
        for (int k = 1; k < w; k++) p = compose(p, sAgg[k]);
        v = compose(p, v);
    }
}

// Phase 1:
//   blocks [0,128):      backbone block-local scans (128 nodes each)
//   blocks [128,128+2048): side chains, 16 lanes per chain (8 chains/block),
//                          parallel build + 4-round segmented Kogge-Stone
__global__ void __launch_bounds__(128)
k_phase1(const float* __restrict__ dofs,
         const float* __restrict__ full_dofs,
         const int* __restrict__ doftype) {
    __shared__ M34 sAgg[4];
    int blk = blockIdx.x;
    int tid = threadIdx.x;

    if (blk < 128) {
        int t = blk * 128 + tid;       // 0..16383
        int n = t + 1;                 // backbone node 1..16384
        int dt = doftype[n];
        M34 v = build_ht(n, dofs, full_dofs, dt);
        block_scan_128(v, tid, sAgg);
#pragma unroll
        for (int c = 0; c < 9; c++) g_L[c][t] = v.r[c];
#pragma unroll
        for (int c = 0; c < 3; c++) g_L[9 + c][t] = v.t[c];
        if (tid == 127) {
#pragma unroll
            for (int c = 0; c < 9; c++) g_Agg[blk][c] = v.r[c];
#pragma unroll
            for (int c = 0; c < 3; c++) g_Agg[blk][9 + c] = v.t[c];
        }
    } else {
        int sblk   = blk - 128;            // 0..2047
        int group  = tid >> 4;             // 0..7
        int lane16 = tid & 15;             // atom-in-chain (15 real + 1 pad)
        int chain  = sblk * 8 + group;     // 0..16383

        M34 v;
        if (lane16 < S_SIDE) {
            int ns = 1 + B_CHAIN + chain * S_SIDE + lane16;
            int dt = doftype[ns];
            v = build_ht(ns, dofs, full_dofs, dt);
        } else {
            v = m_identity();
        }
        // segmented Kogge-Stone over 16-lane groups
#pragma unroll
        for (int d = 1; d < 16; d <<= 1) {
            M34 o = shflup(v, d, 16);
            if (lane16 >= d) v = compose(o, v);
        }
        if (lane16 < S_SIDE) {
            float* st = &g_St[chain][lane16 * 3];
            st[0] = v.t[0];
            st[1] = v.t[1];
            st[2] = v.t[2];
        }
    }
}

// Phase 2: exclusive scan of the 128 block aggregates (single block)
__global__ void __launch_bounds__(128)
k_phase2() {
    __shared__ M34 sAgg[4];
    int tid = threadIdx.x;
    M34 v;
#pragma unroll
    for (int c = 0; c < 9; c++) v.r[c] = g_Agg[tid][c];
#pragma unroll
    for (int c = 0; c < 3; c++) v.t[c] = g_Agg[tid][9 + c];
    block_scan_128(v, tid, sAgg);
    if (tid == 0) {
        M34 I = m_identity();
#pragma unroll
        for (int c = 0; c < 9; c++) g_P[0][c] = I.r[c];
#pragma unroll
        for (int c = 0; c < 3; c++) g_P[0][9 + c] = I.t[c];
    }
    if (tid < 127) {
#pragma unroll
        for (int c = 0; c < 9; c++) g_P[tid + 1][c] = v.r[c];
#pragma unroll
        for (int c = 0; c < 3; c++) g_P[tid + 1][9 + c] = v.t[c];
    }
}

// Phase 3: apply block prefixes; write backbone coords; fix up side-chain
// translations with a matvec (chain t's parent is backbone node t+1 == this thread's node)
__global__ void __launch_bounds__(128)
k_phase3(const int* __restrict__ kin_id, float* __restrict__ out) {
    int blk = blockIdx.x, tid = threadIdx.x;
    int t = blk * 128 + tid;   // 0..16383
    int n = t + 1;             // backbone node

    M34 P;
#pragma unroll
    for (int c = 0; c < 9; c++) P.r[c] = g_P[blk][c];
#pragma unroll
    for (int c = 0; c < 3; c++) P.t[c] = g_P[blk][9 + c];

    M34 L;
#pragma unroll
    for (int c = 0; c < 9; c++) L.r[c] = g_L[c][t];
#pragma unroll
    for (int c = 0; c < 3; c++) L.t[c] = g_L[9 + c][t];

    M34 G = compose(P, L);

    int kid = kin_id[n];
    out[3 * kid + 0] = G.t[0];
    out[3 * kid + 1] = G.t[1];
    out[3 * kid + 2] = G.t[2];

    const float* st = &g_St[t][0];
#pragma unroll
    for (int s = 0; s < S_SIDE; s++) {
        float x = st[s * 3 + 0];
        float y = st[s * 3 + 1];
        float z = st[s * 3 + 2];
        float vx = fmaf(G.r[0], x, fmaf(G.r[1], y, fmaf(G.r[2], z, G.t[0])));
        float vy = fmaf(G.r[3], x, fmaf(G.r[4], y, fmaf(G.r[5], z, G.t[1])));
        float vz = fmaf(G.r[6], x, fmaf(G.r[7], y, fmaf(G.r[8], z, G.t[2])));
        int ns = 1 + B_CHAIN + t * S_SIDE + s;
        int k2 = kin_id[ns];
        out[3 * k2 + 0] = vx;
        out[3 * k2 + 1] = vy;
        out[3 * k2 + 2] = vz;
    }
}

extern "C" void kernel_launch(void* const* d_in, const int* in_sizes, int n_in,
                              void* d_out, int out_size) {
    const float* dofs      = (const float*)d_in[0];
    const float* full_dofs = (const float*)d_in[1];
    const int*   doftype   = (const int*)d_in[4];
    const int*   kin_id    = (const int*)d_in[8];
    float* out = (float*)d_out;

    k_phase1<<<128 + 2048, 128>>>(dofs, full_dofs, doftype);
    k_phase2<<<1, 128>>>();
    k_phase3<<<128, 128>>>(kin_id, out);
}

// round 3
// speedup vs baseline: 1.6277x; 1.0150x over previous
#include <cuda_runtime.h>
#include <math.h>

#define B_CHAIN 16384
#define S_SIDE  15
#define NATM    (1 + B_CHAIN + B_CHAIN * S_SIDE)

// 3x4 affine transform: rotation r[9] row-major, translation t[3]
struct M34 { float r[9]; float t[3]; };

__device__ __forceinline__ M34 m_identity() {
    M34 m;
    m.r[0]=1.f; m.r[1]=0.f; m.r[2]=0.f;
    m.r[3]=0.f; m.r[4]=1.f; m.r[5]=0.f;
    m.r[6]=0.f; m.r[7]=0.f; m.r[8]=1.f;
    m.t[0]=0.f; m.t[1]=0.f; m.t[2]=0.f;
    return m;
}

// C = A @ B  (A is the earlier transform)
__device__ __forceinline__ M34 compose(const M34& A, const M34& B) {
    M34 C;
#pragma unroll
    for (int i = 0; i < 3; i++) {
#pragma unroll
        for (int j = 0; j < 3; j++) {
            C.r[i*3+j] = fmaf(A.r[i*3+0], B.r[0*3+j],
                          fmaf(A.r[i*3+1], B.r[1*3+j],
                               A.r[i*3+2] * B.r[2*3+j]));
        }
        C.t[i] = fmaf(A.r[i*3+0], B.t[0],
                  fmaf(A.r[i*3+1], B.t[1],
                   fmaf(A.r[i*3+2], B.t[2], A.t[i])));
    }
    return C;
}

__device__ __forceinline__ M34 shflup(const M34& v, int d, int width) {
    M34 o;
#pragma unroll
    for (int k = 0; k < 9; k++) o.r[k] = __shfl_up_sync(0xffffffffu, v.r[k], d, width);
#pragma unroll
    for (int k = 0; k < 3; k++) o.t[k] = __shfl_up_sync(0xffffffffu, v.t[k], d, width);
    return o;
}

// Bond matrix: Rx(a)*Rz(b)*T(c,0,0)*Rx(d) given sin/cos of the three angles.
__device__ __forceinline__ M34 bond_mat(float sa, float ca, float sb, float cb,
                                        float sd, float cd, float c) {
    M34 m;
    m.r[0] = cb;      m.r[1] = -cd * sb;                 m.r[2] = sd * sb;
    m.r[3] = ca * sb; m.r[4] = fmaf(cd*ca, cb, -sd*sa);  m.r[5] = fmaf(-sd*ca, cb, -cd*sa);
    m.r[6] = sa * sb; m.r[7] = fmaf(cd*sa, cb,  sd*ca);  m.r[8] = fmaf(-sd*sa, cb,  cd*ca);
    m.t[0] = c * cb;
    m.t[1] = c * ca * sb;
    m.t[2] = c * sa * sb;
    return m;
}

// Accurate build (backbone — error accumulates over 16k composes)
__device__ __forceinline__ M34 build_ht_acc(int n,
                                            const float* __restrict__ dofs,
                                            const float* __restrict__ full_dofs,
                                            int dt) {
    if (dt == 2) {
        float4 dv = *(const float4*)(dofs + 4 * (n - 1));
        float sa, ca, sb, cb, sd, cd;
        sincosf(dv.x, &sa, &ca);
        sincosf(dv.y, &sb, &cb);
        sincosf(dv.w, &sd, &cd);
        return bond_mat(sa, ca, sb, cb, sd, cd, dv.z);
    } else if (dt == 1) {
        float4 dv = *(const float4*)(dofs + 4 * (n - 1));
        float f = full_dofs[9 * n + 4];
        float e = full_dofs[9 * n + 5];
        float sd, cd, sf, cf, se, ce;
        sincosf(dv.w, &sd, &cd);
        sincosf(f, &sf, &cf);
        sincosf(e, &se, &ce);
        M34 m;
        m.r[0] = ce * cf;  m.r[1] = fmaf(sd*ce, sf, -cd*se);  m.r[2] = fmaf(cd*ce, sf,  sd*se);
        m.r[3] = se * cf;  m.r[4] = fmaf(sd*se, sf,  cd*ce);  m.r[5] = fmaf(cd*se, sf, -sd*ce);
        m.r[6] = -sf;      m.r[7] = sd * cf;                  m.r[8] = cd * cf;
        m.t[0] = dv.x; m.t[1] = dv.y; m.t[2] = dv.z;
        return m;
    }
    return m_identity();
}

// Fast build (side chains — depth <= 15, MUFU sincos fine)
__device__ __forceinline__ M34 build_ht_fast(int n,
                                             const float* __restrict__ dofs,
                                             const float* __restrict__ full_dofs,
                                             int dt) {
    if (dt == 2) {
        float4 dv = *(const float4*)(dofs + 4 * (n - 1));
        float sa, ca, sb, cb, sd, cd;
        __sincosf(dv.x, &sa, &ca);
        __sincosf(dv.y, &sb, &cb);
        __sincosf(dv.w, &sd, &cd);
        return bond_mat(sa, ca, sb, cb, sd, cd, dv.z);
    } else if (dt == 1) {
        float4 dv = *(const float4*)(dofs + 4 * (n - 1));
        float f = full_dofs[9 * n + 4];
        float e = full_dofs[9 * n + 5];
        float sd, cd, sf, cf, se, ce;
        __sincosf(dv.w, &sd, &cd);
        __sincosf(f, &sf, &cf);
        __sincosf(e, &se, &ce);
        M34 m;
        m.r[0] = ce * cf;  m.r[1] = fmaf(sd*ce, sf, -cd*se);  m.r[2] = fmaf(cd*ce, sf,  sd*se);
        m.r[3] = se * cf;  m.r[4] = fmaf(sd*se, sf,  cd*ce);  m.r[5] = fmaf(cd*se, sf, -sd*ce);
        m.r[6] = -sf;      m.r[7] = sd * cf;                  m.r[8] = cd * cf;
        m.t[0] = dv.x; m.t[1] = dv.y; m.t[2] = dv.z;
        return m;
    }
    return m_identity();
}

// Scratch (allocation-free: __device__ globals)
__device__ float g_L[12][B_CHAIN];          // backbone block-local inclusive products (SoA)
__device__ float g_Agg[128][12];            // per-block aggregates
__device__ float g_St[S_SIDE][3][B_CHAIN];  // side-chain inclusive translations (SoA)

// Inclusive Kogge-Stone scan across 128 threads (4 warps)
__device__ __forceinline__ void block_scan_128(M34& v, int tid, M34* sAgg) {
    int lane = tid & 31, w = tid >> 5;
#pragma unroll
    for (int d = 1; d < 32; d <<= 1) {
        M34 o = shflup(v, d, 32);
        if (lane >= d) v = compose(o, v);
    }
    if (lane == 31) sAgg[w] = v;
    __syncthreads();
    if (w > 0) {
        M34 p = sAgg[0];
        for (int k = 1; k < w; k++) p = compose(p, sAgg[k]);
        v = compose(p, v);
    }
}

// Phase 1:
//   blocks [0,128):        backbone block-local scans (128 nodes each, accurate sincos)
//   blocks [128,128+2048): side chains, 16 lanes per chain (8 chains/block),
//                          parallel build (fast sincos) + 4-round segmented Kogge-Stone
__global__ void __launch_bounds__(128)
k_phase1(const float* __restrict__ dofs,
         const float* __restrict__ full_dofs,
         const int* __restrict__ doftype) {
    __shared__ M34 sAgg[4];
    int blk = blockIdx.x;
    int tid = threadIdx.x;

    if (blk < 128) {
        int t = blk * 128 + tid;       // 0..16383
        int n = t + 1;                 // backbone node 1..16384
        int dt = doftype[n];
        M34 v = build_ht_acc(n, dofs, full_dofs, dt);
        block_scan_128(v, tid, sAgg);
#pragma unroll
        for (int c = 0; c < 9; c++) g_L[c][t] = v.r[c];
#pragma unroll
        for (int c = 0; c < 3; c++) g_L[9 + c][t] = v.t[c];
        if (tid == 127) {
#pragma unroll
            for (int c = 0; c < 9; c++) g_Agg[blk][c] = v.r[c];
#pragma unroll
            for (int c = 0; c < 3; c++) g_Agg[blk][9 + c] = v.t[c];
        }
    } else {
        int sblk   = blk - 128;            // 0..2047
        int group  = tid >> 4;             // 0..7
        int lane16 = tid & 15;             // atom-in-chain (15 real + 1 pad)
        int chain  = sblk * 8 + group;     // 0..16383

        M34 v;
        if (lane16 < S_SIDE) {
            int ns = 1 + B_CHAIN + chain * S_SIDE + lane16;
            int dt = doftype[ns];
            v = build_ht_fast(ns, dofs, full_dofs, dt);
        } else {
            v = m_identity();
        }
        // segmented Kogge-Stone over 16-lane groups
#pragma unroll
        for (int d = 1; d < 16; d <<= 1) {
            M34 o = shflup(v, d, 16);
            if (lane16 >= d) v = compose(o, v);
        }
        if (lane16 < S_SIDE) {
            g_St[lane16][0][chain] = v.t[0];
            g_St[lane16][1][chain] = v.t[1];
            g_St[lane16][2][chain] = v.t[2];
        }
    }
}

// Phase 2+3 fused: each block redundantly scans the 128 aggregates to get its
// own exclusive prefix, then applies it, writes backbone coords, and fixes up
// side-chain translations with matvecs.
__global__ void __launch_bounds__(128)
k_final(const int* __restrict__ kin_id, float* __restrict__ out) {
    __shared__ M34 sAgg[4];
    __shared__ float sP[12];
    int blk = blockIdx.x, tid = threadIdx.x;

    // Redundant per-block scan of aggregates -> exclusive prefix for this block
    {
        M34 a;
#pragma unroll
        for (int c = 0; c < 9; c++) a.r[c] = g_Agg[tid][c];
#pragma unroll
        for (int c = 0; c < 3; c++) a.t[c] = g_Agg[tid][9 + c];
        block_scan_128(a, tid, sAgg);
        if (blk == 0) {
            if (tid == 0) {
                M34 I = m_identity();
#pragma unroll
                for (int c = 0; c < 9; c++) sP[c] = I.r[c];
#pragma unroll
                for (int c = 0; c < 3; c++) sP[9 + c] = I.t[c];
            }
        } else if (tid == blk - 1) {
#pragma unroll
            for (int c = 0; c < 9; c++) sP[c] = a.r[c];
#pragma unroll
            for (int c = 0; c < 3; c++) sP[9 + c] = a.t[c];
        }
        __syncthreads();
    }

    M34 P;
#pragma unroll
    for (int c = 0; c < 9; c++) P.r[c] = sP[c];
#pragma unroll
    for (int c = 0; c < 3; c++) P.t[c] = sP[9 + c];

    int t = blk * 128 + tid;   // 0..16383
    int n = t + 1;             // backbone node

    M34 L;
#pragma unroll
    for (int c = 0; c < 9; c++) L.r[c] = g_L[c][t];
#pragma unroll
    for (int c = 0; c < 3; c++) L.t[c] = g_L[9 + c][t];

    M34 G = compose(P, L);

    int kid = kin_id[n];
    out[3 * kid + 0] = G.t[0];
    out[3 * kid + 1] = G.t[1];
    out[3 * kid + 2] = G.t[2];

#pragma unroll
    for (int s = 0; s < S_SIDE; s++) {
        float x = g_St[s][0][t];
        float y = g_St[s][1][t];
        float z = g_St[s][2][t];
        float vx = fmaf(G.r[0], x, fmaf(G.r[1], y, fmaf(G.r[2], z, G.t[0])));
        float vy = fmaf(G.r[3], x, fmaf(G.r[4], y, fmaf(G.r[5], z, G.t[1])));
        float vz = fmaf(G.r[6], x, fmaf(G.r[7], y, fmaf(G.r[8], z, G.t[2])));
        int ns = 1 + B_CHAIN + t * S_SIDE + s;
        int k2 = kin_id[ns];
        out[3 * k2 + 0] = vx;
        out[3 * k2 + 1] = vy;
        out[3 * k2 + 2] = vz;
    }
}

extern "C" void kernel_launch(void* const* d_in, const int* in_sizes, int n_in,
                              void* d_out, int out_size) {
    const float* dofs      = (const float*)d_in[0];
    const float* full_dofs = (const float*)d_in[1];
    const int*   doftype   = (const int*)d_in[4];
    const int*   kin_id    = (const int*)d_in[8];
    float* out = (float*)d_out;

    k_phase1<<<128 + 2048, 128>>>(dofs, full_dofs, doftype);
    k_final<<<128, 128>>>(kin_id, out);
}

// round 6
// speedup vs baseline: 1.6497x; 1.0135x over previous
#include <cuda_runtime.h>
#include <math.h>

#define B_CHAIN 16384
#define S_SIDE  15
#define NATM    (1 + B_CHAIN + B_CHAIN * S_SIDE)

// 3x4 affine transform: rotation r[9] row-major, translation t[3]
struct M34 { float r[9]; float t[3]; };

__device__ __forceinline__ M34 m_identity() {
    M34 m;
    m.r[0]=1.f; m.r[1]=0.f; m.r[2]=0.f;
    m.r[3]=0.f; m.r[4]=1.f; m.r[5]=0.f;
    m.r[6]=0.f; m.r[7]=0.f; m.r[8]=1.f;
    m.t[0]=0.f; m.t[1]=0.f; m.t[2]=0.f;
    return m;
}

// C = A @ B  (A is the earlier transform)
__device__ __forceinline__ M34 compose(const M34& A, const M34& B) {
    M34 C;
#pragma unroll
    for (int i = 0; i < 3; i++) {
#pragma unroll
        for (int j = 0; j < 3; j++) {
            C.r[i*3+j] = fmaf(A.r[i*3+0], B.r[0*3+j],
                          fmaf(A.r[i*3+1], B.r[1*3+j],
                               A.r[i*3+2] * B.r[2*3+j]));
        }
        C.t[i] = fmaf(A.r[i*3+0], B.t[0],
                  fmaf(A.r[i*3+1], B.t[1],
                   fmaf(A.r[i*3+2], B.t[2], A.t[i])));
    }
    return C;
}

__device__ __forceinline__ M34 shflup(const M34& v, int d, int width) {
    M34 o;
#pragma unroll
    for (int k = 0; k < 9; k++) o.r[k] = __shfl_up_sync(0xffffffffu, v.r[k], d, width);
#pragma unroll
    for (int k = 0; k < 3; k++) o.t[k] = __shfl_up_sync(0xffffffffu, v.t[k], d, width);
    return o;
}

// FMA-pipe sincos: magic-number quadrant reduction + cephes minimax polys on
// [-pi/4, pi/4]. Valid for |x| << 2^22 (here |x| < 3). Max err ~1.2e-7.
// CORRECTED Horner forms (R4 had an extra factor of z in both polys):
//   sin(r) = r + r*z*(s2 + z*(s3 + z*s4)),   z = r^2
//   cos(r) = 1 - z/2 + z^2*(c2 + z*(c3 + z*c4))
__device__ __forceinline__ void poly_sincos(float x, float* sp, float* cp) {
    const float MAGIC = 12582912.0f;             // 1.5 * 2^23
    float k = fmaf(x, 0.63661977236758134f, MAGIC);
    int   q = __float_as_int(k);                 // low mantissa bits = round(x*2/pi) mod 4 (in low 2 bits)
    float n = k - MAGIC;
    float r = fmaf(n, -1.57079637e+00f, x);      // pi/2 hi
    r       = fmaf(n,  4.37113883e-08f, r);      // pi/2 lo correction
    float z = r * r;
    // sin
    float ps = fmaf(z, fmaf(z, -1.9515295891e-4f, 8.3321608736e-3f), -1.6666654611e-1f);
    ps = fmaf(ps * z, r, r);
    // cos
    float pc = fmaf(z, fmaf(z, 2.44331571e-5f, -1.38873163e-3f), 4.16666457e-2f);
    pc = fmaf(pc, z * z, fmaf(-0.5f, z, 1.0f));
    bool swap = (q & 1);
    float s = swap ? pc : ps;
    float c = swap ? ps : pc;
    if (q & 2) s = -s;
    if ((q + 1) & 2) c = -c;
    *sp = s; *cp = c;
}

// Bond matrix: Rx(a)*Rz(b)*T(c,0,0)*Rx(d) given sin/cos of the three angles.
__device__ __forceinline__ M34 bond_mat(float sa, float ca, float sb, float cb,
                                        float sd, float cd, float c) {
    M34 m;
    m.r[0] = cb;      m.r[1] = -cd * sb;                 m.r[2] = sd * sb;
    m.r[3] = ca * sb; m.r[4] = fmaf(cd*ca, cb, -sd*sa);  m.r[5] = fmaf(-sd*ca, cb, -cd*sa);
    m.r[6] = sa * sb; m.r[7] = fmaf(cd*sa, cb,  sd*ca);  m.r[8] = fmaf(-sd*sa, cb,  cd*ca);
    m.t[0] = c * cb;
    m.t[1] = c * ca * sb;
    m.t[2] = c * sa * sb;
    return m;
}

// Accurate build (backbone — error accumulates over 16k composes)
__device__ __forceinline__ M34 build_ht_acc(int n,
                                            const float* __restrict__ dofs,
                                            const float* __restrict__ full_dofs,
                                            int dt) {
    if (dt == 2) {
        float4 dv = *(const float4*)(dofs + 4 * (n - 1));
        float sa, ca, sb, cb, sd, cd;
        sincosf(dv.x, &sa, &ca);
        sincosf(dv.y, &sb, &cb);
        sincosf(dv.w, &sd, &cd);
        return bond_mat(sa, ca, sb, cb, sd, cd, dv.z);
    } else if (dt == 1) {
        float4 dv = *(const float4*)(dofs + 4 * (n - 1));
        float f = full_dofs[9 * n + 4];
        float e = full_dofs[9 * n + 5];
        float sd, cd, sf, cf, se, ce;
        sincosf(dv.w, &sd, &cd);
        sincosf(f, &sf, &cf);
        sincosf(e, &se, &ce);
        M34 m;
        m.r[0] = ce * cf;  m.r[1] = fmaf(sd*ce, sf, -cd*se);  m.r[2] = fmaf(cd*ce, sf,  sd*se);
        m.r[3] = se * cf;  m.r[4] = fmaf(sd*se, sf,  cd*ce);  m.r[5] = fmaf(cd*se, sf, -sd*ce);
        m.r[6] = -sf;      m.r[7] = sd * cf;                  m.r[8] = cd * cf;
        m.t[0] = dv.x; m.t[1] = dv.y; m.t[2] = dv.z;
        return m;
    }
    return m_identity();
}

// Fast build (side chains — depth <= 15, FMA-pipe poly sincos)
__device__ __forceinline__ M34 build_ht_fast(int n,
                                             const float* __restrict__ dofs,
                                             const float* __restrict__ full_dofs,
                                             int dt) {
    if (dt == 2) {
        float4 dv = *(const float4*)(dofs + 4 * (n - 1));
        float sa, ca, sb, cb, sd, cd;
        poly_sincos(dv.x, &sa, &ca);
        poly_sincos(dv.y, &sb, &cb);
        poly_sincos(dv.w, &sd, &cd);
        return bond_mat(sa, ca, sb, cb, sd, cd, dv.z);
    } else if (dt == 1) {
        float4 dv = *(const float4*)(dofs + 4 * (n - 1));
        float f = full_dofs[9 * n + 4];
        float e = full_dofs[9 * n + 5];
        float sd, cd, sf, cf, se, ce;
        poly_sincos(dv.w, &sd, &cd);
        poly_sincos(f, &sf, &cf);
        poly_sincos(e, &se, &ce);
        M34 m;
        m.r[0] = ce * cf;  m.r[1] = fmaf(sd*ce, sf, -cd*se);  m.r[2] = fmaf(cd*ce, sf,  sd*se);
        m.r[3] = se * cf;  m.r[4] = fmaf(sd*se, sf,  cd*ce);  m.r[5] = fmaf(cd*se, sf, -sd*ce);
        m.r[6] = -sf;      m.r[7] = sd * cf;                  m.r[8] = cd * cf;
        m.t[0] = dv.x; m.t[1] = dv.y; m.t[2] = dv.z;
        return m;
    }
    return m_identity();
}

// Scratch (allocation-free: __device__ globals)
__device__ float g_L[12][B_CHAIN];          // backbone block-local inclusive products (SoA)
__device__ float g_Agg[128][12];            // per-block aggregates
__device__ float g_St[B_CHAIN][48];         // side-chain inclusive translations (AoS, 45 used)

// Inclusive Kogge-Stone scan across 128 threads (4 warps)
__device__ __forceinline__ void block_scan_128(M34& v, int tid, M34* sAgg) {
    int lane = tid & 31, w = tid >> 5;
#pragma unroll
    for (int d = 1; d < 32; d <<= 1) {
        M34 o = shflup(v, d, 32);
        if (lane >= d) v = compose(o, v);
    }
    if (lane == 31) sAgg[w] = v;
    __syncthreads();
    if (w > 0) {
        M34 p = sAgg[0];
        for (int k = 1; k < w; k++) p = compose(p, sAgg[k]);
        v = compose(p, v);
    }
}

// Phase 1:
//   blocks [0,128):        backbone block-local scans (128 nodes each, accurate sincos)
//   blocks [128,128+2048): side chains, 16 lanes per chain (8 chains/block),
//                          parallel build (poly sincos) + 4-round segmented Kogge-Stone
__global__ void __launch_bounds__(128)
k_phase1(const float* __restrict__ dofs,
         const float* __restrict__ full_dofs,
         const int* __restrict__ doftype) {
    __shared__ M34 sAgg[4];
    int blk = blockIdx.x;
    int tid = threadIdx.x;

    if (blk < 128) {
        int t = blk * 128 + tid;       // 0..16383
        int n = t + 1;                 // backbone node 1..16384
        int dt = doftype[n];
        M34 v = build_ht_acc(n, dofs, full_dofs, dt);
        block_scan_128(v, tid, sAgg);
#pragma unroll
        for (int c = 0; c < 9; c++) g_L[c][t] = v.r[c];
#pragma unroll
        for (int c = 0; c < 3; c++) g_L[9 + c][t] = v.t[c];
        if (tid == 127) {
#pragma unroll
            for (int c = 0; c < 9; c++) g_Agg[blk][c] = v.r[c];
#pragma unroll
            for (int c = 0; c < 3; c++) g_Agg[blk][9 + c] = v.t[c];
        }
    } else {
        int sblk   = blk - 128;            // 0..2047
        int group  = tid >> 4;             // 0..7
        int lane16 = tid & 15;             // atom-in-chain (15 real + 1 pad)
        int chain  = sblk * 8 + group;     // 0..16383

        M34 v;
        if (lane16 < S_SIDE) {
            int ns = 1 + B_CHAIN + chain * S_SIDE + lane16;
            int dt = doftype[ns];
            v = build_ht_fast(ns, dofs, full_dofs, dt);
        } else {
            v = m_identity();
        }
        // segmented Kogge-Stone over 16-lane groups
#pragma unroll
        for (int d = 1; d < 16; d <<= 1) {
            M34 o = shflup(v, d, 16);
            if (lane16 >= d) v = compose(o, v);
        }
        if (lane16 < S_SIDE) {
            float* st = &g_St[chain][lane16 * 3];
            st[0] = v.t[0];
            st[1] = v.t[1];
            st[2] = v.t[2];
        }
    }
}

// Phase 2+3: 2048 blocks; each block redundantly scans the 128 aggregates for
// its exclusive chunk prefix, then 16 lanes per backbone node: lane 15 writes
// the backbone coord, lanes 0..14 each matvec one side-chain translation.
__global__ void __launch_bounds__(128)
k_apply(const int* __restrict__ kin_id, float* __restrict__ out) {
    __shared__ M34 sAgg[4];
    __shared__ float sP[12];
    int blk = blockIdx.x, tid = threadIdx.x;
    int chunk = blk >> 4;   // = (blk*8)/128 : backbone 128-chunk this block maps into

    // Redundant scan of aggregates -> exclusive prefix for this chunk
    {
        M34 a;
#pragma unroll
        for (int c = 0; c < 9; c++) a.r[c] = g_Agg[tid][c];
#pragma unroll
        for (int c = 0; c < 3; c++) a.t[c] = g_Agg[tid][9 + c];
        block_scan_128(a, tid, sAgg);
        if (chunk == 0) {
            if (tid == 0) {
                M34 I = m_identity();
#pragma unroll
                for (int c = 0; c < 9; c++) sP[c] = I.r[c];
#pragma unroll
                for (int c = 0; c < 3; c++) sP[9 + c] = I.t[c];
            }
        } else if (tid == chunk - 1) {
#pragma unroll
            for (int c = 0; c < 9; c++) sP[c] = a.r[c];
#pragma unroll
            for (int c = 0; c < 3; c++) sP[9 + c] = a.t[c];
        }
        __syncthreads();
    }

    M34 P;
#pragma unroll
    for (int c = 0; c < 9; c++) P.r[c] = sP[c];
#pragma unroll
    for (int c = 0; c < 3; c++) P.t[c] = sP[9 + c];

    int group  = tid >> 4;
    int lane16 = tid & 15;
    int t = blk * 8 + group;   // backbone index 0..16383

    M34 L;
#pragma unroll
    for (int c = 0; c < 9; c++) L.r[c] = g_L[c][t];
#pragma unroll
    for (int c = 0; c < 3; c++) L.t[c] = g_L[9 + c][t];

    M34 G = compose(P, L);

    if (lane16 == 15) {
        int kid = kin_id[t + 1];
        out[3 * kid + 0] = G.t[0];
        out[3 * kid + 1] = G.t[1];
        out[3 * kid + 2] = G.t[2];
    } else {
        const float* st = &g_St[t][lane16 * 3];
        float x = st[0], y = st[1], z = st[2];
        float vx = fmaf(G.r[0], x, fmaf(G.r[1], y, fmaf(G.r[2], z, G.t[0])));
        float vy = fmaf(G.r[3], x, fmaf(G.r[4], y, fmaf(G.r[5], z, G.t[1])));
        float vz = fmaf(G.r[6], x, fmaf(G.r[7], y, fmaf(G.r[8], z, G.t[2])));
        int ns = 1 + B_CHAIN + t * S_SIDE + lane16;
        int k2 = kin_id[ns];
        out[3 * k2 + 0] = vx;
        out[3 * k2 + 1] = vy;
        out[3 * k2 + 2] = vz;
    }
}

extern "C" void kernel_launch(void* const* d_in, const int* in_sizes, int n_in,
                              void* d_out, int out_size) {
    const float* dofs      = (const float*)d_in[0];
    const float* full_dofs = (const float*)d_in[1];
    const int*   doftype   = (const int*)d_in[4];
    const int*   kin_id    = (const int*)d_in[8];
    float* out = (float*)d_out;

    k_phase1<<<128 + 2048, 128>>>(dofs, full_dofs, doftype);
    k_apply<<<2048, 128>>>(kin_id, out);
}